// round 2
// baseline (speedup 1.0000x reference)
#include <cuda_runtime.h>
#include <cstdint>

// ---------------- problem constants ----------------
#define NN 16
#define CC 64
#define HW 3136       // 56*56
#define WID 56

// ---------------- device scratch (no allocs allowed) ----------------
__device__ float g_maxabs_x, g_maxw1, g_maxw2, g_max_r1, g_max_r2;
__device__ unsigned g_qxp[NN*16*HW];     // packed int8 qx: (n, c4, hw), byte j = channel 4*c4+j
__device__ unsigned g_q1p[NN*16*HW];     // packed uint8 q1
__device__ float    g_t1 [NN*CC*HW];     // bn1 output (pre-relu), fp32
__device__ unsigned g_qw1p[9216];        // packed weights: [c4][pos][o]
__device__ unsigned g_qw2p[9216];
__device__ int g_wsum1[4608], g_wsum2[4608];   // [cb][pos], cb = c*8+bit
__device__ int g_stats1[9*512], g_stats2[9*512]; // 9 stats x 512 channel-bits

__device__ __forceinline__ void atomicMaxF(float* a, float v) {
    atomicMax((int*)a, __float_as_int(v));   // valid for non-negative floats
}

__device__ __forceinline__ int dp4a_ss(unsigned a, unsigned b, int c) {
    int r;
    asm("dp4a.s32.s32 %0, %1, %2, %3;" : "=r"(r) : "r"(a), "r"(b), "r"(c));
    return r;
}
__device__ __forceinline__ int dp4a_us(unsigned a, unsigned b, int c) {
    int r;
    asm("dp4a.u32.s32 %0, %1, %2, %3;" : "=r"(r) : "r"(a), "r"(b), "r"(c));
    return r;
}
template<int PASS>
__device__ __forceinline__ int DP(unsigned a, unsigned b, int c) {
    return (PASS == 1) ? dp4a_ss(a, b, c) : dp4a_us(a, b, c);
}

// ---------------- init: reset atomic-max scalars each replay ----------------
__global__ void initKernel() {
    if (threadIdx.x == 0) { g_maxabs_x = 0.f; g_max_r1 = 0.f; g_max_r2 = 0.f; }
}

// ---------------- max |x| reduction ----------------
__global__ void maxAbsXKernel(const float4* __restrict__ x) {
    const int n4 = NN*CC*HW/4;
    float m = 0.f;
    for (int i = blockIdx.x*blockDim.x + threadIdx.x; i < n4; i += gridDim.x*blockDim.x) {
        float4 v = x[i];
        m = fmaxf(m, fmaxf(fmaxf(fabsf(v.x), fabsf(v.y)), fmaxf(fabsf(v.z), fabsf(v.w))));
    }
    #pragma unroll
    for (int o = 16; o; o >>= 1) m = fmaxf(m, __shfl_xor_sync(0xffffffffu, m, o));
    __shared__ float sm[8];
    if ((threadIdx.x & 31) == 0) sm[threadIdx.x >> 5] = m;
    __syncthreads();
    if (threadIdx.x == 0) {
        float mm = sm[0];
        #pragma unroll
        for (int i = 1; i < 8; i++) mm = fmaxf(mm, sm[i]);
        atomicMaxF(&g_maxabs_x, mm);
    }
}

// ---------------- max |w| : block 0 -> w1, block 1 -> w2 ----------------
__global__ void maxAbsWKernel(const float* __restrict__ w1, const float* __restrict__ w2) {
    const float* w = blockIdx.x ? w2 : w1;
    float m = 0.f;
    for (int i = threadIdx.x; i < 36864; i += blockDim.x) m = fmaxf(m, fabsf(w[i]));
    #pragma unroll
    for (int o = 16; o; o >>= 1) m = fmaxf(m, __shfl_xor_sync(0xffffffffu, m, o));
    __shared__ float sm[8];
    if ((threadIdx.x & 31) == 0) sm[threadIdx.x >> 5] = m;
    __syncthreads();
    if (threadIdx.x == 0) {
        float mm = sm[0];
        #pragma unroll
        for (int i = 1; i < 8; i++) mm = fmaxf(mm, sm[i]);
        if (blockIdx.x) g_maxw2 = mm; else g_maxw1 = mm;
    }
}

// ---------------- quantize x -> packed int8 ----------------
__global__ void quantXKernel(const float* __restrict__ x) {
    int idx = blockIdx.x*blockDim.x + threadIdx.x;
    if (idx >= NN*16*HW) return;
    int n = idx / (16*HW);
    int rem = idx - n*16*HW;
    int c4 = rem / HW;
    int hw = rem - c4*HW;
    float s = g_maxabs_x * (1.0f/127.0f);
    const float* xb = x + ((n*CC + c4*4)*HW + hw);
    unsigned word = 0;
    #pragma unroll
    for (int j = 0; j < 4; j++) {
        float q = rintf(xb[j*HW] / s);
        q = fminf(127.f, fmaxf(-127.f, q));
        word |= (((unsigned)(int)q) & 0xffu) << (8*j);
    }
    g_qxp[idx] = word;
}

// ---------------- quantize + pack weights: layout [c4][pos][o] ----------------
__global__ void quantWKernel(const float* __restrict__ w1, const float* __restrict__ w2) {
    int idx = blockIdx.x*blockDim.x + threadIdx.x;
    if (idx >= 2*9216) return;
    int sel = idx / 9216;
    int widx = idx - sel*9216;
    int c4  = widx / 576;
    int rem = widx - c4*576;
    int pos = rem / 64;
    int o   = rem - pos*64;
    const float* w = sel ? w2 : w1;
    float s = (sel ? g_maxw2 : g_maxw1) * (1.0f/127.0f);
    unsigned word = 0;
    #pragma unroll
    for (int j = 0; j < 4; j++) {
        float q = rintf(w[o*576 + (c4*4+j)*9 + pos] / s);
        q = fminf(127.f, fmaxf(-127.f, q));
        word |= (((unsigned)(int)q) & 0xffu) << (8*j);
    }
    if (sel) g_qw2p[widx] = word; else g_qw1p[widx] = word;
}

// ---------------- Wsum[cb][pos] = sum_o bit_b(qw[o,c,pos]) ----------------
__global__ void wsumKernel() {
    int idx = blockIdx.x*blockDim.x + threadIdx.x;
    if (idx >= 2*4608) return;
    int sel = idx / 4608;
    int i2  = idx - sel*4608;
    int cb  = i2 / 9;
    int pos = i2 - cb*9;
    int c = cb >> 3, b = cb & 7;
    const unsigned* wp = sel ? g_qw2p : g_qw1p;
    int base = (c >> 2)*576 + pos*64;
    int sh = (c & 3)*8;
    int s = 0;
    for (int o = 0; o < 64; o++) {
        unsigned u = (wp[base + o] >> sh) & 0xffu;
        s += (u >> b) & 1u;
    }
    if (sel) g_wsum2[i2] = s; else g_wsum1[i2] = s;
}

// ---------------- per-channel-bit activation stats (9 per cb) ----------------
// stats layout: s*512 + c*8 + b; s: 0=all,1=row0,2=row55,3=col0,4=col55,
//               5=(0,0),6=(0,55),7=(55,0),8=(55,55)
template<int WHICH>
__global__ void statsKernel() {
    const unsigned* __restrict__ qp = (WHICH == 1) ? g_qxp : g_q1p;
    int* __restrict__ stats = (WHICH == 1) ? g_stats1 : g_stats2;
    int c = blockIdx.x;
    int c4 = c >> 2, sh = (c & 3)*8;
    __shared__ int sc[72];
    if (threadIdx.x < 72) sc[threadIdx.x] = 0;
    __syncthreads();

    int cnt[8] = {0,0,0,0,0,0,0,0};
    for (int i = threadIdx.x; i < NN*HW; i += blockDim.x) {
        int n = i / HW, hw = i - n*HW;
        unsigned u = (qp[(n*16 + c4)*HW + hw] >> sh) & 0xffu;
        #pragma unroll
        for (int k = 0; k < 8; k++) cnt[k] += (u >> k) & 1u;
    }
    #pragma unroll
    for (int k = 0; k < 8; k++) atomicAdd(&sc[k], cnt[k]);

    // border rows (h=0, h=55)
    for (int i = threadIdx.x; i < NN*WID; i += blockDim.x) {
        int n = i / WID, w = i - n*WID;
        int base = (n*16 + c4)*HW;
        unsigned u0 = (qp[base + w] >> sh) & 0xffu;
        unsigned u1 = (qp[base + 3080 + w] >> sh) & 0xffu;
        #pragma unroll
        for (int k = 0; k < 8; k++) {
            atomicAdd(&sc[ 8 + k], (int)((u0 >> k) & 1u));
            atomicAdd(&sc[16 + k], (int)((u1 >> k) & 1u));
        }
    }
    // border cols (w=0, w=55)
    for (int i = threadIdx.x; i < NN*WID; i += blockDim.x) {
        int n = i / WID, h = i - n*WID;
        int base = (n*16 + c4)*HW;
        unsigned u0 = (qp[base + h*WID] >> sh) & 0xffu;
        unsigned u1 = (qp[base + h*WID + 55] >> sh) & 0xffu;
        #pragma unroll
        for (int k = 0; k < 8; k++) {
            atomicAdd(&sc[24 + k], (int)((u0 >> k) & 1u));
            atomicAdd(&sc[32 + k], (int)((u1 >> k) & 1u));
        }
    }
    // corners
    if (threadIdx.x < 16) {
        int n = threadIdx.x;
        int base = (n*16 + c4)*HW;
        unsigned u00 = (qp[base +    0] >> sh) & 0xffu;
        unsigned u0b = (qp[base +   55] >> sh) & 0xffu;
        unsigned ub0 = (qp[base + 3080] >> sh) & 0xffu;
        unsigned ubb = (qp[base + 3135] >> sh) & 0xffu;
        #pragma unroll
        for (int k = 0; k < 8; k++) {
            atomicAdd(&sc[40 + k], (int)((u00 >> k) & 1u));
            atomicAdd(&sc[48 + k], (int)((u0b >> k) & 1u));
            atomicAdd(&sc[56 + k], (int)((ub0 >> k) & 1u));
            atomicAdd(&sc[64 + k], (int)((ubb >> k) & 1u));
        }
    }
    __syncthreads();
    if (threadIdx.x < 72) {
        int s = threadIdx.x >> 3, k = threadIdx.x & 7;
        stats[s*512 + c*8 + k] = sc[threadIdx.x];
    }
}

// ---------------- int8 DP4A conv + fused BN (+identity) + max-relu ----------------
// PASS 1: qx (s8) * qw1 (s8) -> g_t1, atomicMax -> g_max_r1
// PASS 2: q1 (u8) * qw2 (s8) + identity -> dOut, atomicMax -> g_max_r2
template<int PASS>
__global__ void __launch_bounds__(256) convKernel(
    const float* __restrict__ gamma, const float* __restrict__ beta,
    const float* __restrict__ mean,  const float* __restrict__ var,
    float* __restrict__ dOut)
{
    const unsigned* __restrict__ inP = (PASS == 1) ? g_qxp : g_q1p;
    const uint4* __restrict__ wP = (const uint4*)((PASS == 1) ? g_qw1p : g_qw2p);
    int n  = blockIdx.x / 28;
    int r0 = (blockIdx.x - n*28) * 2;

    __shared__ unsigned sIn[16*4*58];   // [c4][4 rows][58 cols] with -1 halo
    for (int i = threadIdx.x; i < 16*4*58; i += 256) {
        int c4 = i / 232;
        int r2 = i - c4*232;
        int rr = r2 / 58;
        int cc = r2 - rr*58;
        int gr = r0 - 1 + rr, gc = cc - 1;
        unsigned v = 0;
        if ((unsigned)gr < 56u && (unsigned)gc < 56u)
            v = inP[(n*16 + c4)*HW + gr*WID + gc];
        sIn[i] = v;
    }
    __syncthreads();

    int ot    = threadIdx.x >> 4;       // 0..15 -> output channels ot*4..ot*4+3
    int pg    = threadIdx.x & 15;       // 0..15 -> (row, 7-col group)
    int lrow  = pg >> 3;                // 0..1
    int cbase = (pg & 7) * 7;           // 0,7,...,49

    int acc[4][7];
    #pragma unroll
    for (int j = 0; j < 4; j++)
        #pragma unroll
        for (int p = 0; p < 7; p++) acc[j][p] = 0;

    const unsigned* sp = sIn + lrow*58 + cbase;
    #pragma unroll 1
    for (int c4 = 0; c4 < 16; c4++) {
        const unsigned* spc = sp + c4*232;
        const uint4* wpc = wP + c4*144 + ot;
        #pragma unroll
        for (int dr = 0; dr < 3; dr++) {
            uint4 w0 = __ldg(wpc + (dr*3 + 0)*16);
            uint4 w1 = __ldg(wpc + (dr*3 + 1)*16);
            uint4 w2 = __ldg(wpc + (dr*3 + 2)*16);
            unsigned iv[9];
            #pragma unroll
            for (int dc = 0; dc < 9; dc++) iv[dc] = spc[dr*58 + dc];
            #pragma unroll
            for (int px = 0; px < 7; px++) {
                unsigned a0 = iv[px], a1 = iv[px+1], a2 = iv[px+2];
                acc[0][px] = DP<PASS>(a0, w0.x, acc[0][px]);
                acc[1][px] = DP<PASS>(a0, w0.y, acc[1][px]);
                acc[2][px] = DP<PASS>(a0, w0.z, acc[2][px]);
                acc[3][px] = DP<PASS>(a0, w0.w, acc[3][px]);
                acc[0][px] = DP<PASS>(a1, w1.x, acc[0][px]);
                acc[1][px] = DP<PASS>(a1, w1.y, acc[1][px]);
                acc[2][px] = DP<PASS>(a1, w1.z, acc[2][px]);
                acc[3][px] = DP<PASS>(a1, w1.w, acc[3][px]);
                acc[0][px] = DP<PASS>(a2, w2.x, acc[0][px]);
                acc[1][px] = DP<PASS>(a2, w2.y, acc[1][px]);
                acc[2][px] = DP<PASS>(a2, w2.z, acc[2][px]);
                acc[3][px] = DP<PASS>(a2, w2.w, acc[3][px]);
            }
        }
    }

    float sp1, sx = 0.f;
    if (PASS == 1) {
        sp1 = (g_maxabs_x * (1.f/127.f)) * (g_maxw1 * (1.f/127.f));
    } else {
        sp1 = (g_max_r1 * (1.f/255.f)) * (g_maxw2 * (1.f/127.f));
        sx  = g_maxabs_x * (1.f/127.f);
    }
    float A[4], B[4];
    #pragma unroll
    for (int j = 0; j < 4; j++) {
        int o = ot*4 + j;
        float inv = gamma[o] / sqrtf(var[o] + 1e-5f);
        A[j] = sp1 * inv;
        B[j] = beta[o] - mean[o]*inv;
    }

    float* dstp = (PASS == 1) ? g_t1 : dOut;
    float mx = 0.f;
    int hwbase = (r0 + lrow)*WID + cbase;
    #pragma unroll
    for (int px = 0; px < 7; px++) {
        int hw = hwbase + px;
        unsigned idw = 0;
        if (PASS == 2) idw = g_qxp[(n*16 + ot)*HW + hw];
        #pragma unroll
        for (int j = 0; j < 4; j++) {
            float t = (float)acc[j][px] * A[j] + B[j];
            if (PASS == 2) {
                int qb = (int)((int8_t)((idw >> (8*j)) & 0xffu));
                t += (float)qb * sx;
            }
            dstp[(n*CC + ot*4 + j)*HW + hw] = t;
            mx = fmaxf(mx, t);
        }
    }
    #pragma unroll
    for (int o = 16; o; o >>= 1) mx = fmaxf(mx, __shfl_xor_sync(0xffffffffu, mx, o));
    __shared__ float smx[8];
    if ((threadIdx.x & 31) == 0) smx[threadIdx.x >> 5] = mx;
    __syncthreads();
    if (threadIdx.x == 0) {
        float m = smx[0];
        #pragma unroll
        for (int i = 1; i < 8; i++) m = fmaxf(m, smx[i]);
        atomicMaxF((PASS == 1) ? &g_max_r1 : &g_max_r2, m);
    }
}

// ---------------- QuantReLU on t1 -> packed uint8 q1 ----------------
__global__ void quantRelu1Kernel() {
    int idx = blockIdx.x*blockDim.x + threadIdx.x;
    if (idx >= NN*16*HW) return;
    int n = idx / (16*HW);
    int rem = idx - n*16*HW;
    int c4 = rem / HW;
    int hw = rem - c4*HW;
    float s = g_max_r1 * (1.f/255.f);
    const float* tb = g_t1 + (n*CC + c4*4)*HW + hw;
    unsigned word = 0;
    #pragma unroll
    for (int j = 0; j < 4; j++) {
        float r = fmaxf(tb[j*HW], 0.f);
        float q = fminf(255.f, rintf(r / s));
        word |= ((unsigned)(int)q) << (8*j);
    }
    g_q1p[idx] = word;
}

// ---------------- final QuantReLU on d_out (in place) ----------------
__global__ void finalQuantKernel(float* __restrict__ out) {
    int i = blockIdx.x*blockDim.x + threadIdx.x;
    if (i >= NN*CC*HW/4) return;
    float s = g_max_r2 * (1.f/255.f);
    float4* o4 = (float4*)out;
    float4 v = o4[i];
    v.x = fminf(255.f, rintf(fmaxf(v.x, 0.f) / s)) * s;
    v.y = fminf(255.f, rintf(fmaxf(v.y, 0.f) / s)) * s;
    v.z = fminf(255.f, rintf(fmaxf(v.z, 0.f) / s)) * s;
    v.w = fminf(255.f, rintf(fmaxf(v.w, 0.f) / s)) * s;
    o4[i] = v;
}

// ---------------- HM_act / HM_energy from factorized stats ----------------
__device__ __forceinline__ long long energyFor(const int* stats, const int* wsum, int cb) {
    int S   = stats[        cb];
    int r0  = stats[ 512  + cb];
    int r55 = stats[1024  + cb];
    int c0  = stats[1536  + cb];
    int c55 = stats[2048  + cb];
    int s00 = stats[2560  + cb];
    int s0b = stats[3072  + cb];
    int sb0 = stats[3584  + cb];
    int sbb = stats[4096  + cb];
    long long en = 0;
    #pragma unroll
    for (int kh = 0; kh < 3; kh++) {
        #pragma unroll
        for (int kw = 0; kw < 3; kw++) {
            int xs = S;
            if (kh == 2) xs -= r0;  else if (kh == 0) xs -= r55;
            if (kw == 2) xs -= c0;  else if (kw == 0) xs -= c55;
            if (kh == 2 && kw == 2) xs += s00;
            if (kh == 2 && kw == 0) xs += s0b;
            if (kh == 0 && kw == 2) xs += sb0;
            if (kh == 0 && kw == 0) xs += sbb;
            en += (long long)wsum[cb*9 + kh*3 + kw] * (long long)xs;
        }
    }
    return en;
}

__global__ void finalizeKernel(float* __restrict__ out) {
    int cb = threadIdx.x;   // 512 threads
    long long act = (long long)g_stats1[cb] + (long long)g_stats2[cb];
    long long en  = energyFor(g_stats1, g_wsum1, cb) + energyFor(g_stats2, g_wsum2, cb);
    __shared__ long long sa[512], se[512];
    sa[cb] = act; se[cb] = en;
    __syncthreads();
    for (int step = 256; step; step >>= 1) {
        if (cb < step) { sa[cb] += sa[cb + step]; se[cb] += se[cb + step]; }
        __syncthreads();
    }
    if (cb == 0) {
        out[NN*CC*HW    ] = (float)sa[0];   // HM_act
        out[NN*CC*HW + 1] = (float)se[0];   // HM_energy
    }
}

// ---------------- launch ----------------
extern "C" void kernel_launch(void* const* d_in, const int* in_sizes, int n_in,
                              void* d_out, int out_size) {
    const float* x  = (const float*)d_in[0];
    const float* w1 = (const float*)d_in[1];
    const float* w2 = (const float*)d_in[2];
    const float* g1 = (const float*)d_in[3];
    const float* b1 = (const float*)d_in[4];
    const float* m1 = (const float*)d_in[5];
    const float* v1 = (const float*)d_in[6];
    const float* g2 = (const float*)d_in[7];
    const float* b2 = (const float*)d_in[8];
    const float* m2 = (const float*)d_in[9];
    const float* v2 = (const float*)d_in[10];
    float* out = (float*)d_out;

    initKernel<<<1, 32>>>();
    maxAbsXKernel<<<512, 256>>>((const float4*)x);
    maxAbsWKernel<<<2, 256>>>(w1, w2);
    quantXKernel<<<3136, 256>>>(x);
    quantWKernel<<<72, 256>>>(w1, w2);
    wsumKernel<<<36, 256>>>();
    statsKernel<1><<<64, 256>>>();
    convKernel<1><<<448, 256>>>(g1, b1, m1, v1, nullptr);
    quantRelu1Kernel<<<3136, 256>>>();
    statsKernel<2><<<64, 256>>>();
    convKernel<2><<<448, 256>>>(g2, b2, m2, v2, out);
    finalQuantKernel<<<3136, 256>>>(out);
    finalizeKernel<<<1, 512>>>(out);
}